// round 5
// baseline (speedup 1.0000x reference)
#include <cuda_runtime.h>

// MultiScaleDeformableAttention
// value:               (8, 22223, 8, 32) f32
// sampling_locations:  (8, 900, 8, 4, 4, 2) f32
// attention_weights:   (8, 900, 8, 4, 4) f32
// out:                 (8, 900, 256) f32  == (b, q, h, d)

#define BS   8
#define NQ   900
#define NH   8
#define D    32
#define NL   4
#define NPT  4
#define NUM_KEYS 22223

__device__ __constant__ int c_H[NL]     = {100, 50, 25, 13};
__device__ __constant__ int c_W[NL]     = {167, 84, 42, 21};
__device__ __constant__ int c_START[NL] = {0, 16700, 20900, 21950};

// Each thread owns 8 channels (2 x float4) of one (b,q,h) output vector.
// 4 lanes cover the full 32-channel vector; each corner gather is one
// coalesced 128B line per 4-lane group, with 8 LDG.128 in flight per point.
__global__ void __launch_bounds__(256, 4) msda_kernel(
    const float* __restrict__ value,
    const float* __restrict__ loc,
    const float* __restrict__ aw,
    float* __restrict__ out)
{
    const int tid = blockIdx.x * blockDim.x + threadIdx.x;
    const int total = BS * NQ * NH * (D / 8);
    if (tid >= total) return;

    const int chunk = tid & 3;        // which 8-channel slice
    const int bqh   = tid >> 2;
    const int h     = bqh % NH;
    const int bq    = bqh / NH;
    const int q     = bq % NQ;
    const int b     = bq / NQ;

    const float* loc_p = loc + (((b * NQ + q) * NH + h) * NL * NPT) * 2;
    const float* aw_p  = aw  + (((b * NQ + q) * NH + h) * NL * NPT);

    const float* vbase = value + (b * NUM_KEYS * NH + h) * D + chunk * 8;

    float4 accA = make_float4(0.f, 0.f, 0.f, 0.f);
    float4 accB = make_float4(0.f, 0.f, 0.f, 0.f);

    #pragma unroll
    for (int l = 0; l < NL; ++l) {
        const int H = c_H[l];
        const int W = c_W[l];
        const float* vlvl = vbase + c_START[l] * (NH * D);

        #pragma unroll
        for (int p = 0; p < NPT; ++p) {
            const int s = l * NPT + p;
            const float lx = __ldg(&loc_p[s * 2 + 0]);
            const float ly = __ldg(&loc_p[s * 2 + 1]);
            const float wa = __ldg(&aw_p[s]);

            const float x = lx * (float)W - 0.5f;
            const float y = ly * (float)H - 0.5f;
            const float xf = floorf(x);
            const float yf = floorf(y);
            const int x0 = (int)xf;
            const int y0 = (int)yf;
            const float tx = x - xf;
            const float ty = y - yf;

            const float w00 = (1.f - tx) * (1.f - ty) * wa;
            const float w10 = tx * (1.f - ty) * wa;
            const float w01 = (1.f - tx) * ty * wa;
            const float w11 = tx * ty * wa;

            const bool vx0 = (x0 >= 0) && (x0 < W);
            const bool vx1 = (x0 + 1 >= 0) && (x0 + 1 < W);
            const bool vy0 = (y0 >= 0) && (y0 < H);
            const bool vy1 = (y0 + 1 >= 0) && (y0 + 1 < H);

            const int row0 = y0 * W;
            const int row1 = row0 + W;

            float4 a00 = make_float4(0.f,0.f,0.f,0.f), b00 = a00;
            float4 a10 = a00, b10 = a00;
            float4 a01 = a00, b01 = a00;
            float4 a11 = a00, b11 = a00;

            if (vy0 && vx0) {
                const float4* pv = (const float4*)(vlvl + (row0 + x0    ) * (NH * D));
                a00 = pv[0]; b00 = pv[1];
            }
            if (vy0 && vx1) {
                const float4* pv = (const float4*)(vlvl + (row0 + x0 + 1) * (NH * D));
                a10 = pv[0]; b10 = pv[1];
            }
            if (vy1 && vx0) {
                const float4* pv = (const float4*)(vlvl + (row1 + x0    ) * (NH * D));
                a01 = pv[0]; b01 = pv[1];
            }
            if (vy1 && vx1) {
                const float4* pv = (const float4*)(vlvl + (row1 + x0 + 1) * (NH * D));
                a11 = pv[0]; b11 = pv[1];
            }

            accA.x += w00 * a00.x + w10 * a10.x + w01 * a01.x + w11 * a11.x;
            accA.y += w00 * a00.y + w10 * a10.y + w01 * a01.y + w11 * a11.y;
            accA.z += w00 * a00.z + w10 * a10.z + w01 * a01.z + w11 * a11.z;
            accA.w += w00 * a00.w + w10 * a10.w + w01 * a01.w + w11 * a11.w;
            accB.x += w00 * b00.x + w10 * b10.x + w01 * b01.x + w11 * b11.x;
            accB.y += w00 * b00.y + w10 * b10.y + w01 * b01.y + w11 * b11.y;
            accB.z += w00 * b00.z + w10 * b10.z + w01 * b01.z + w11 * b11.z;
            accB.w += w00 * b00.w + w10 * b10.w + w01 * b01.w + w11 * b11.w;
        }
    }

    float* op = out + ((b * NQ + q) * NH + h) * D + chunk * 8;
    ((float4*)op)[0] = accA;
    ((float4*)op)[1] = accB;
}

extern "C" void kernel_launch(void* const* d_in, const int* in_sizes, int n_in,
                              void* d_out, int out_size)
{
    const float* value = (const float*)d_in[0];
    const float* loc   = (const float*)d_in[1];
    const float* aw    = (const float*)d_in[2];
    float* out = (float*)d_out;

    const int total = BS * NQ * NH * (D / 8);   // 230400
    const int block = 256;
    const int grid  = (total + block - 1) / block;   // 900
    msda_kernel<<<grid, block>>>(value, loc, aw, out);
}

// round 7
// speedup vs baseline: 1.2400x; 1.2400x over previous
#include <cuda_runtime.h>

// MultiScaleDeformableAttention
// value:               (8, 22223, 8, 32) f32
// sampling_locations:  (8, 900, 8, 4, 4, 2) f32
// attention_weights:   (8, 900, 8, 4, 4) f32
// out:                 (8, 900, 256) f32  == (b, q, h, d)

#define BS   8
#define NQ   900
#define NH   8
#define D    32
#define NL   4
#define NPT  4
#define NUM_KEYS 22223
#define NHD  (NH * D)          // 256 floats stride per pixel

#define GROUPS_PER_BLOCK 32    // (b,q,h) groups per block
#define PTS_PER_GROUP    16    // 4 levels x 4 points
#define PTS_PER_BLOCK    (GROUPS_PER_BLOCK * PTS_PER_GROUP)   // 512

__device__ __constant__ int c_H[NL]     = {100, 50, 25, 13};
__device__ __constant__ int c_W[NL]     = {167, 84, 42, 21};
__device__ __constant__ int c_START[NL] = {0, 16700, 20900, 21950};

__global__ void __launch_bounds__(256) msda_kernel(
    const float* __restrict__ value,
    const float* __restrict__ loc,
    const float* __restrict__ aw,
    float* __restrict__ out)
{
    __shared__ float4 s_w[PTS_PER_BLOCK];   // w00,w10,w01,w11 (validity folded)
    __shared__ int4   s_o[PTS_PER_BLOCK];   // element offsets of 4 corners

    const int tid = threadIdx.x;

    // ---------------- Phase 1: compute 512 point descriptors (2 per thread)
    #pragma unroll
    for (int pi = tid; pi < PTS_PER_BLOCK; pi += 256) {
        const int g   = pi >> 4;            // group within block
        const int s   = pi & 15;            // point within group
        const int l   = s >> 2;             // level
        const int bqh = blockIdx.x * GROUPS_PER_BLOCK + g;

        const float2 lxy = __ldg((const float2*)(loc + (bqh * PTS_PER_GROUP + s) * 2));
        const float  wa  = __ldg(aw + bqh * PTS_PER_GROUP + s);

        const int H = c_H[l];
        const int W = c_W[l];

        const float x = lxy.x * (float)W - 0.5f;
        const float y = lxy.y * (float)H - 0.5f;
        const float xf = floorf(x);
        const float yf = floorf(y);
        const int x0 = (int)xf;
        const int y0 = (int)yf;
        const float tx = x - xf;
        const float ty = y - yf;

        // validity folded into weights; loads will use clamped indices
        const float wx0 = (x0 >= 0 && x0 < W)         ? (1.f - tx) : 0.f;
        const float wx1 = (x0 + 1 >= 0 && x0 + 1 < W) ? tx         : 0.f;
        const float wy0 = (y0 >= 0 && y0 < H)         ? (1.f - ty) : 0.f;
        const float wy1 = (y0 + 1 >= 0 && y0 + 1 < H) ? ty         : 0.f;

        const int xc0 = min(max(x0,     0), W - 1);
        const int xc1 = min(max(x0 + 1, 0), W - 1);
        const int yc0 = min(max(y0,     0), H - 1);
        const int yc1 = min(max(y0 + 1, 0), H - 1);

        const int base = c_START[l];
        const int r0 = base + yc0 * W;
        const int r1 = base + yc1 * W;

        s_w[pi] = make_float4(wx0 * wy0 * wa, wx1 * wy0 * wa,
                              wx0 * wy1 * wa, wx1 * wy1 * wa);
        s_o[pi] = make_int4((r0 + xc0) * NHD, (r0 + xc1) * NHD,
                            (r1 + xc0) * NHD, (r1 + xc1) * NHD);
    }

    __syncthreads();

    // ---------------- Phase 2: pure gather + FMA
    const int g     = tid >> 3;            // group (0..31)
    const int chunk = tid & 7;             // which float4 of the 32 channels
    const int bqh   = blockIdx.x * GROUPS_PER_BLOCK + g;
    const int h     = bqh & (NH - 1);
    const int bq    = bqh >> 3;
    const int q     = bq % NQ;
    const int b     = bq / NQ;

    const float* vbase = value + (b * NUM_KEYS * NH + h) * D + chunk * 4;

    float4 acc = make_float4(0.f, 0.f, 0.f, 0.f);

    #pragma unroll
    for (int s = 0; s < PTS_PER_GROUP; ++s) {
        const float4 w = s_w[g * PTS_PER_GROUP + s];
        const int4   o = s_o[g * PTS_PER_GROUP + s];

        const float4 v00 = *(const float4*)(vbase + o.x);
        const float4 v10 = *(const float4*)(vbase + o.y);
        const float4 v01 = *(const float4*)(vbase + o.z);
        const float4 v11 = *(const float4*)(vbase + o.w);

        acc.x += w.x * v00.x + w.y * v10.x + w.z * v01.x + w.w * v11.x;
        acc.y += w.x * v00.y + w.y * v10.y + w.z * v01.y + w.w * v11.y;
        acc.z += w.x * v00.z + w.y * v10.z + w.z * v01.z + w.w * v11.z;
        acc.w += w.x * v00.w + w.y * v10.w + w.z * v01.w + w.w * v11.w;
    }

    float* op = out + ((b * NQ + q) * NH + h) * D + chunk * 4;
    *(float4*)op = acc;
}

extern "C" void kernel_launch(void* const* d_in, const int* in_sizes, int n_in,
                              void* d_out, int out_size)
{
    const float* value = (const float*)d_in[0];
    const float* loc   = (const float*)d_in[1];
    const float* aw    = (const float*)d_in[2];
    float* out = (float*)d_out;

    const int total = BS * NQ * NH * (D / 4);   // 460800
    const int block = 256;
    const int grid  = total / block;            // 1800
    msda_kernel<<<grid, block>>>(value, loc, aw, out);
}

// round 8
// speedup vs baseline: 1.3125x; 1.0584x over previous
#include <cuda_runtime.h>

// MultiScaleDeformableAttention
// value:               (8, 22223, 8, 32) f32
// sampling_locations:  (8, 900, 8, 4, 4, 2) f32
// attention_weights:   (8, 900, 8, 4, 4) f32
// out:                 (8, 900, 256) f32  == (b, q, h, d)

#define BS   8
#define NQ   900
#define NH   8
#define D    32
#define NL   4
#define NPT  4
#define NUM_KEYS 22223
#define NHD  (NH * D)          // 256 floats stride per pixel

#define GROUPS_PER_BLOCK 32    // (b,q,h) groups per block
#define PTS_PER_GROUP    16    // 4 levels x 4 points
#define PTS_PER_BLOCK    (GROUPS_PER_BLOCK * PTS_PER_GROUP)   // 512

__device__ __constant__ int c_H[NL]     = {100, 50, 25, 13};
__device__ __constant__ int c_W[NL]     = {167, 84, 42, 21};
__device__ __constant__ int c_START[NL] = {0, 16700, 20900, 21950};

__global__ void __launch_bounds__(256, 5) msda_kernel(
    const float* __restrict__ value,
    const float* __restrict__ loc,
    const float* __restrict__ aw,
    float* __restrict__ out)
{
    __shared__ float4 s_w[PTS_PER_BLOCK];   // w00,w10,w01,w11 (validity folded)
    __shared__ int4   s_o[PTS_PER_BLOCK];   // element offsets of 4 corners

    const int tid = threadIdx.x;

    // ---------------- Phase 1: compute 512 point descriptors (2 per thread)
    #pragma unroll
    for (int pi = tid; pi < PTS_PER_BLOCK; pi += 256) {
        const int g   = pi >> 4;            // group within block
        const int s   = pi & 15;            // point within group
        const int l   = s >> 2;             // level
        const int bqh = blockIdx.x * GROUPS_PER_BLOCK + g;

        const float2 lxy = __ldg((const float2*)(loc + (bqh * PTS_PER_GROUP + s) * 2));
        const float  wa  = __ldg(aw + bqh * PTS_PER_GROUP + s);

        const int H = c_H[l];
        const int W = c_W[l];

        const float x = lxy.x * (float)W - 0.5f;
        const float y = lxy.y * (float)H - 0.5f;
        const float xf = floorf(x);
        const float yf = floorf(y);
        const int x0 = (int)xf;
        const int y0 = (int)yf;
        const float tx = x - xf;
        const float ty = y - yf;

        // validity folded into weights; loads will use clamped indices
        const float wx0 = (x0 >= 0 && x0 < W)         ? (1.f - tx) : 0.f;
        const float wx1 = (x0 + 1 >= 0 && x0 + 1 < W) ? tx         : 0.f;
        const float wy0 = (y0 >= 0 && y0 < H)         ? (1.f - ty) : 0.f;
        const float wy1 = (y0 + 1 >= 0 && y0 + 1 < H) ? ty         : 0.f;

        const int xc0 = min(max(x0,     0), W - 1);
        const int xc1 = min(max(x0 + 1, 0), W - 1);
        const int yc0 = min(max(y0,     0), H - 1);
        const int yc1 = min(max(y0 + 1, 0), H - 1);

        const int base = c_START[l];
        const int r0 = base + yc0 * W;
        const int r1 = base + yc1 * W;

        s_w[pi] = make_float4(wx0 * wy0 * wa, wx1 * wy0 * wa,
                              wx0 * wy1 * wa, wx1 * wy1 * wa);
        s_o[pi] = make_int4((r0 + xc0) * NHD, (r0 + xc1) * NHD,
                            (r1 + xc0) * NHD, (r1 + xc1) * NHD);
    }

    __syncthreads();

    // ---------------- Phase 2: gather + FMA, two points in flight (8 LDG.128)
    const int g     = tid >> 3;            // group (0..31)
    const int chunk = tid & 7;             // which float4 of the 32 channels
    const int bqh   = blockIdx.x * GROUPS_PER_BLOCK + g;
    const int h     = bqh & (NH - 1);
    const int bq    = bqh >> 3;
    const int q     = bq % NQ;
    const int b     = bq / NQ;

    const float* vbase = value + (b * NUM_KEYS * NH + h) * D + chunk * 4;
    const int gbase = g * PTS_PER_GROUP;

    float4 acc = make_float4(0.f, 0.f, 0.f, 0.f);

    #pragma unroll
    for (int s = 0; s < PTS_PER_GROUP; s += 2) {
        const float4 wA = s_w[gbase + s];
        const int4   oA = s_o[gbase + s];
        const float4 wB = s_w[gbase + s + 1];
        const int4   oB = s_o[gbase + s + 1];

        // 8 independent 128-bit loads in flight before any consumption
        const float4 a00 = *(const float4*)(vbase + oA.x);
        const float4 a10 = *(const float4*)(vbase + oA.y);
        const float4 a01 = *(const float4*)(vbase + oA.z);
        const float4 a11 = *(const float4*)(vbase + oA.w);
        const float4 b00 = *(const float4*)(vbase + oB.x);
        const float4 b10 = *(const float4*)(vbase + oB.y);
        const float4 b01 = *(const float4*)(vbase + oB.z);
        const float4 b11 = *(const float4*)(vbase + oB.w);

        acc.x += wA.x * a00.x + wA.y * a10.x + wA.z * a01.x + wA.w * a11.x;
        acc.y += wA.x * a00.y + wA.y * a10.y + wA.z * a01.y + wA.w * a11.y;
        acc.z += wA.x * a00.z + wA.y * a10.z + wA.z * a01.z + wA.w * a11.z;
        acc.w += wA.x * a00.w + wA.y * a10.w + wA.z * a01.w + wA.w * a11.w;

        acc.x += wB.x * b00.x + wB.y * b10.x + wB.z * b01.x + wB.w * b11.x;
        acc.y += wB.x * b00.y + wB.y * b10.y + wB.z * b01.y + wB.w * b11.y;
        acc.z += wB.x * b00.z + wB.y * b10.z + wB.z * b01.z + wB.w * b11.z;
        acc.w += wB.x * b00.w + wB.y * b10.w + wB.z * b01.w + wB.w * b11.w;
    }

    float* op = out + ((b * NQ + q) * NH + h) * D + chunk * 4;
    *(float4*)op = acc;
}

extern "C" void kernel_launch(void* const* d_in, const int* in_sizes, int n_in,
                              void* d_out, int out_size)
{
    const float* value = (const float*)d_in[0];
    const float* loc   = (const float*)d_in[1];
    const float* aw    = (const float*)d_in[2];
    float* out = (float*)d_out;

    const int total = BS * NQ * NH * (D / 4);   // 460800
    const int block = 256;
    const int grid  = total / block;            // 1800
    msda_kernel<<<grid, block>>>(value, loc, aw, out);
}